// round 6
// baseline (speedup 1.0000x reference)
#include <cuda_runtime.h>
#include <cuda_bf16.h>
#include <math.h>

// ---------------- problem constants ----------------
#define T_LEN   1024
#define HID     2048
#define NH      64
#define HKV     4
#define GQ      16      // heads per kv group
#define DIM     64
#define BS      64      // block size
#define NB      16      // T / BS
#define SSEL    8       // top-k blocks
#define WIN     512     // sliding window
#define SCALE   0.125f  // 64^-0.5
#define NEG     -1e30f

// ---------------- scratch (device globals; no allocation) ----------------
__device__ float d_q[T_LEN * NH * DIM];       // roped q
__device__ float d_k[T_LEN * HKV * DIM];      // roped k
__device__ float d_v[T_LEN * HKV * DIM];
__device__ float d_g[T_LEN * NH * 3];         // sigmoid gates
__device__ float d_kc[NB * HKV * DIM];
__device__ float d_vc[NB * HKV * DIM];
__device__ int   d_topidx[T_LEN * HKV * SSEL];
__device__ int   d_topcnt[T_LEN * HKV];
__device__ float d_o[T_LEN * NH * DIM];       // gated combined output

// ---------------- generic tiled SGEMM: C[M,N] = A[M,K] @ B[K,N] ----------
// 64x64 tile, BK=16, 256 threads, 4x4 microtile, float4 IO.
__global__ void sgemm64(const float* __restrict__ A, const float* __restrict__ B,
                        float* __restrict__ C, int M, int N, int K) {
    __shared__ float As[16][64];
    __shared__ float Bs[16][64];
    const int tid = threadIdx.x;
    const int tx = tid & 15, ty = tid >> 4;
    const int row0 = blockIdx.y * 64, col0 = blockIdx.x * 64;

    const int ar = tid >> 2;            // 0..63
    const int ac = (tid & 3) * 4;       // 0..12
    const int br = tid >> 4;            // 0..15
    const int bc = (tid & 15) * 4;      // 0..60

    float acc[4][4];
#pragma unroll
    for (int i = 0; i < 4; i++)
#pragma unroll
        for (int j = 0; j < 4; j++) acc[i][j] = 0.f;

    for (int kk = 0; kk < K; kk += 16) {
        float4 av = *reinterpret_cast<const float4*>(&A[(size_t)(row0 + ar) * K + kk + ac]);
        float4 bv = *reinterpret_cast<const float4*>(&B[(size_t)(kk + br) * N + col0 + bc]);
        __syncthreads();
        As[ac + 0][ar] = av.x; As[ac + 1][ar] = av.y;
        As[ac + 2][ar] = av.z; As[ac + 3][ar] = av.w;
        *reinterpret_cast<float4*>(&Bs[br][bc]) = bv;
        __syncthreads();
#pragma unroll
        for (int k = 0; k < 16; k++) {
            float a0 = As[k][ty * 4 + 0], a1 = As[k][ty * 4 + 1];
            float a2 = As[k][ty * 4 + 2], a3 = As[k][ty * 4 + 3];
            float b0 = Bs[k][tx * 4 + 0], b1 = Bs[k][tx * 4 + 1];
            float b2 = Bs[k][tx * 4 + 2], b3 = Bs[k][tx * 4 + 3];
            acc[0][0] += a0 * b0; acc[0][1] += a0 * b1; acc[0][2] += a0 * b2; acc[0][3] += a0 * b3;
            acc[1][0] += a1 * b0; acc[1][1] += a1 * b1; acc[1][2] += a1 * b2; acc[1][3] += a1 * b3;
            acc[2][0] += a2 * b0; acc[2][1] += a2 * b1; acc[2][2] += a2 * b2; acc[2][3] += a2 * b3;
            acc[3][0] += a3 * b0; acc[3][1] += a3 * b1; acc[3][2] += a3 * b2; acc[3][3] += a3 * b3;
        }
    }
#pragma unroll
    for (int i = 0; i < 4; i++) {
        float4 v = make_float4(acc[i][0], acc[i][1], acc[i][2], acc[i][3]);
        *reinterpret_cast<float4*>(&C[(size_t)(row0 + ty * 4 + i) * N + col0 + tx * 4]) = v;
    }
}

// ---------------- RoPE (in place) ----------------
// x layout: [T, nheads, 64]; pair (i, i+32).
__global__ void rope_kernel(float* __restrict__ x, int nheads) {
    int idx = blockIdx.x * blockDim.x + threadIdx.x;
    int total = T_LEN * nheads * 32;
    if (idx >= total) return;
    int i = idx & 31;
    int th = idx >> 5;          // t*nheads + h
    int t = th / nheads;
    float inv = powf(10000.f, -(float)(2 * i) / 64.f);
    float f = (float)t * inv;
    float sn, cs;
    sincosf(f, &sn, &cs);
    float* p = x + (size_t)th * 64;
    float x1 = p[i], x2 = p[i + 32];
    p[i]      = x1 * cs - x2 * sn;
    p[i + 32] = x1 * sn + x2 * cs;
}

__global__ void sigmoid_kernel(float* __restrict__ g, int n) {
    int idx = blockIdx.x * blockDim.x + threadIdx.x;
    if (idx >= n) return;
    g[idx] = 1.f / (1.f + expf(-g[idx]));
}

// ---------------- block mean pooling ----------------
__global__ void compress_kernel(const float* __restrict__ k, const float* __restrict__ v,
                                float* __restrict__ kc, float* __restrict__ vc) {
    int idx = blockIdx.x * blockDim.x + threadIdx.x;  // NB*HKV*DIM = 4096
    if (idx >= NB * HKV * DIM) return;
    int d = idx & 63;
    int h = (idx >> 6) & 3;
    int n = idx >> 8;
    float sk = 0.f, sv = 0.f;
    for (int j = 0; j < BS; j++) {
        int off = ((n * BS + j) * HKV + h) * DIM + d;
        sk += k[off];
        sv += v[off];
    }
    kc[idx] = sk * (1.f / 64.f);
    vc[idx] = sv * (1.f / 64.f);
}

// ---------------- compressed attention + importance + top-k ----------------
// grid (T, HKV), 256 threads.
__global__ void cmp_attn_kernel(const float* __restrict__ q, const float* __restrict__ kc,
                                const float* __restrict__ vc, const float* __restrict__ gates,
                                float* __restrict__ o, int* __restrict__ topidx,
                                int* __restrict__ topcnt) {
    int t = blockIdx.x, hkv = blockIdx.y, tid = threadIdx.x;
    __shared__ float q_s[GQ * DIM];
    __shared__ float s_s[GQ * NB];
    __shared__ float p_s[GQ * NB];
    __shared__ float imp_s[NB];

    const float* qb = q + ((size_t)t * NH + hkv * GQ) * DIM;
    reinterpret_cast<float4*>(q_s)[tid] = reinterpret_cast<const float4*>(qb)[tid];
    __syncthreads();

    {   // scores
        int g_ = tid >> 4, n = tid & 15;
        float acc = 0.f;
        const float* kr = kc + (n * HKV + hkv) * DIM;
#pragma unroll
        for (int d = 0; d < DIM; d++) acc += q_s[g_ * DIM + d] * kr[d];
        acc *= SCALE;
        bool valid = ((n + 1) * BS - 1) <= t;
        s_s[g_ * NB + n] = valid ? acc : NEG;
    }
    __syncthreads();

    if (tid < GQ) {  // softmax per head
        int g_ = tid;
        if (t < BS - 1) {
            for (int n = 0; n < NB; n++) p_s[g_ * NB + n] = 0.f;
        } else {
            float m = NEG;
            for (int n = 0; n < NB; n++) m = fmaxf(m, s_s[g_ * NB + n]);
            float sum = 0.f;
            float e[NB];
            for (int n = 0; n < NB; n++) { e[n] = expf(s_s[g_ * NB + n] - m); sum += e[n]; }
            float inv = 1.f / sum;
            for (int n = 0; n < NB; n++) p_s[g_ * NB + n] = e[n] * inv;
        }
    }
    __syncthreads();

    if (tid < NB) {  // importance per block
        int n = tid;
        float s = 0.f;
        for (int g_ = 0; g_ < GQ; g_++) s += p_s[g_ * NB + n];
        imp_s[n] = s;
    }
    __syncthreads();

    {   // gated o_cmp (initializes d_o)
        int g_ = tid >> 4, dq = tid & 15;
        float gate = gates[((size_t)t * NH + hkv * GQ + g_) * 3 + 0];
#pragma unroll
        for (int r = 0; r < 4; r++) {
            int d = dq * 4 + r;
            float val = 0.f;
            for (int n = 0; n < NB; n++) val += p_s[g_ * NB + n] * vc[(n * HKV + hkv) * DIM + d];
            o[((size_t)t * NH + hkv * GQ + g_) * DIM + d] = gate * val;
        }
    }

    if (tid == 0) {  // top-k (stable: strict > keeps lowest index on tie)
        int cur = t >> 6;
        float sc[NB];
        for (int n = 0; n < NB; n++) {
            if (n > cur) sc[n] = -INFINITY;
            else if (n == 0 || n == cur) sc[n] = INFINITY;
            else sc[n] = imp_s[n];
        }
        bool used[NB];
        for (int n = 0; n < NB; n++) used[n] = false;
        int cnt = 0;
        for (int s = 0; s < SSEL; s++) {
            float bv = -INFINITY; int bi = -1;
            for (int n = 0; n < NB; n++)
                if (!used[n] && sc[n] > bv) { bv = sc[n]; bi = n; }
            if (bi < 0) break;
            used[bi] = true;
            topidx[((size_t)t * HKV + hkv) * SSEL + cnt] = bi;
            cnt++;
        }
        topcnt[t * HKV + hkv] = cnt;
    }
}

// ---------------- selected-blocks attention (flash-style) ----------------
// grid (T, HKV), 512 threads = 16 warps (one per group head).
__global__ void slc_attn_kernel(const float* __restrict__ q, const float* __restrict__ k,
                                const float* __restrict__ v, const float* __restrict__ gates,
                                const int* __restrict__ topidx, const int* __restrict__ topcnt,
                                float* __restrict__ o) {
    int t = blockIdx.x, hkv = blockIdx.y, tid = threadIdx.x;
    int g_ = tid >> 5, lane = tid & 31;
    __shared__ float q_s[GQ * DIM];
    __shared__ float K_s[64 * 65];
    __shared__ float V_s[64 * 65];
    __shared__ float p_s[GQ * 64];

    if (tid < 256) {
        const float* qb = q + ((size_t)t * NH + hkv * GQ) * DIM;
        reinterpret_cast<float4*>(q_s)[tid] = reinterpret_cast<const float4*>(qb)[tid];
    }

    int cnt = topcnt[t * HKV + hkv];
    float m = NEG, l = 0.f, a0 = 0.f, a1 = 0.f;

    for (int s = 0; s < cnt; s++) {
        int n = topidx[((size_t)t * HKV + hkv) * SSEL + s];
        __syncthreads();
#pragma unroll
        for (int r = 0; r < 8; r++) {
            int e = tid + r * 512;
            int row = e >> 6, d = e & 63;
            int gidx = ((n * BS + row) * HKV + hkv) * DIM + d;
            K_s[row * 65 + d] = k[gidx];
            V_s[row * 65 + d] = v[gidx];
        }
        __syncthreads();

        const float* qg = q_s + g_ * DIM;
        float s0 = 0.f, s1 = 0.f;
#pragma unroll
        for (int d = 0; d < DIM; d++) {
            float qd = qg[d];
            s0 += qd * K_s[lane * 65 + d];
            s1 += qd * K_s[(lane + 32) * 65 + d];
        }
        s0 *= SCALE; s1 *= SCALE;
        int pos0 = n * BS + lane, pos1 = pos0 + 32;
        if (pos0 > t) s0 = NEG;
        if (pos1 > t) s1 = NEG;

        float mx = fmaxf(s0, s1);
#pragma unroll
        for (int off = 16; off; off >>= 1) mx = fmaxf(mx, __shfl_xor_sync(0xffffffffu, mx, off));
        float m_new = fmaxf(m, mx);
        float corr = __expf(m - m_new);
        float p0 = __expf(s0 - m_new), p1 = __expf(s1 - m_new);
        p_s[g_ * 64 + lane] = p0;
        p_s[g_ * 64 + lane + 32] = p1;
        float ps = p0 + p1;
#pragma unroll
        for (int off = 16; off; off >>= 1) ps += __shfl_xor_sync(0xffffffffu, ps, off);
        l = l * corr + ps;
        __syncwarp();
        float acc0 = 0.f, acc1 = 0.f;
#pragma unroll
        for (int j = 0; j < 64; j++) {
            float pj = p_s[g_ * 64 + j];
            acc0 += pj * V_s[j * 65 + lane];
            acc1 += pj * V_s[j * 65 + lane + 32];
        }
        a0 = a0 * corr + acc0;
        a1 = a1 * corr + acc1;
        m = m_new;
    }

    float gate = gates[((size_t)t * NH + hkv * GQ + g_) * 3 + 1];
    float inv = (l > 0.f) ? 1.f / l : 0.f;
    size_t ob = ((size_t)t * NH + hkv * GQ + g_) * DIM;
    o[ob + lane]      += gate * a0 * inv;
    o[ob + lane + 32] += gate * a1 * inv;
}

// ---------------- sliding-window attention ----------------
__global__ void swa_attn_kernel(const float* __restrict__ q, const float* __restrict__ k,
                                const float* __restrict__ v, const float* __restrict__ gates,
                                float* __restrict__ o) {
    int t = blockIdx.x, hkv = blockIdx.y, tid = threadIdx.x;
    int g_ = tid >> 5, lane = tid & 31;
    __shared__ float q_s[GQ * DIM];
    __shared__ float K_s[64 * 65];
    __shared__ float V_s[64 * 65];
    __shared__ float p_s[GQ * 64];

    if (tid < 256) {
        const float* qb = q + ((size_t)t * NH + hkv * GQ) * DIM;
        reinterpret_cast<float4*>(q_s)[tid] = reinterpret_cast<const float4*>(qb)[tid];
    }

    int start = t - (WIN - 1); if (start < 0) start = 0;
    int nch = ((t - start) >> 6) + 1;
    float m = NEG, l = 0.f, a0 = 0.f, a1 = 0.f;

    for (int c = 0; c < nch; c++) {
        int p0r = start + c * 64;
        __syncthreads();
#pragma unroll
        for (int r = 0; r < 8; r++) {
            int e = tid + r * 512;
            int row = e >> 6, d = e & 63;
            int gidx = ((p0r + row) * HKV + hkv) * DIM + d;
            K_s[row * 65 + d] = k[gidx];
            V_s[row * 65 + d] = v[gidx];
        }
        __syncthreads();

        const float* qg = q_s + g_ * DIM;
        float s0 = 0.f, s1 = 0.f;
#pragma unroll
        for (int d = 0; d < DIM; d++) {
            float qd = qg[d];
            s0 += qd * K_s[lane * 65 + d];
            s1 += qd * K_s[(lane + 32) * 65 + d];
        }
        s0 *= SCALE; s1 *= SCALE;
        int pos0 = p0r + lane, pos1 = pos0 + 32;
        if (pos0 > t) s0 = NEG;
        if (pos1 > t) s1 = NEG;

        float mx = fmaxf(s0, s1);
#pragma unroll
        for (int off = 16; off; off >>= 1) mx = fmaxf(mx, __shfl_xor_sync(0xffffffffu, mx, off));
        float m_new = fmaxf(m, mx);
        float corr = __expf(m - m_new);
        float p0 = __expf(s0 - m_new), p1 = __expf(s1 - m_new);
        p_s[g_ * 64 + lane] = p0;
        p_s[g_ * 64 + lane + 32] = p1;
        float ps = p0 + p1;
#pragma unroll
        for (int off = 16; off; off >>= 1) ps += __shfl_xor_sync(0xffffffffu, ps, off);
        l = l * corr + ps;
        __syncwarp();
        float acc0 = 0.f, acc1 = 0.f;
#pragma unroll
        for (int j = 0; j < 64; j++) {
            float pj = p_s[g_ * 64 + j];
            acc0 += pj * V_s[j * 65 + lane];
            acc1 += pj * V_s[j * 65 + lane + 32];
        }
        a0 = a0 * corr + acc0;
        a1 = a1 * corr + acc1;
        m = m_new;
    }

    float gate = gates[((size_t)t * NH + hkv * GQ + g_) * 3 + 2];
    float inv = (l > 0.f) ? 1.f / l : 0.f;
    size_t ob = ((size_t)t * NH + hkv * GQ + g_) * DIM;
    o[ob + lane]      += gate * a0 * inv;
    o[ob + lane + 32] += gate * a1 * inv;
}

// ---------------- launch ----------------
extern "C" void kernel_launch(void* const* d_in, const int* in_sizes, int n_in,
                              void* d_out, int out_size) {
    const float* x  = (const float*)d_in[0];
    const float* Wq = (const float*)d_in[1];
    const float* Wk = (const float*)d_in[2];
    const float* Wv = (const float*)d_in[3];
    const float* Wg = (const float*)d_in[4];
    const float* Wo = (const float*)d_in[5];
    float* out = (float*)d_out;

    float *q, *k, *v, *g, *kc, *vc, *o;
    int *ti, *tc;
    cudaGetSymbolAddress((void**)&q,  d_q);
    cudaGetSymbolAddress((void**)&k,  d_k);
    cudaGetSymbolAddress((void**)&v,  d_v);
    cudaGetSymbolAddress((void**)&g,  d_g);
    cudaGetSymbolAddress((void**)&kc, d_kc);
    cudaGetSymbolAddress((void**)&vc, d_vc);
    cudaGetSymbolAddress((void**)&o,  d_o);
    cudaGetSymbolAddress((void**)&ti, d_topidx);
    cudaGetSymbolAddress((void**)&tc, d_topcnt);

    // projections
    sgemm64<<<dim3(NH * DIM / 64, T_LEN / 64), 256>>>(x, Wq, q, T_LEN, NH * DIM, HID);
    sgemm64<<<dim3(HKV * DIM / 64, T_LEN / 64), 256>>>(x, Wk, k, T_LEN, HKV * DIM, HID);
    sgemm64<<<dim3(HKV * DIM / 64, T_LEN / 64), 256>>>(x, Wv, v, T_LEN, HKV * DIM, HID);
    sgemm64<<<dim3(NH * 3 / 64, T_LEN / 64), 256>>>(x, Wg, g, T_LEN, NH * 3, HID);

    // rope + gates
    rope_kernel<<<(T_LEN * NH * 32 + 255) / 256, 256>>>(q, NH);
    rope_kernel<<<(T_LEN * HKV * 32 + 255) / 256, 256>>>(k, HKV);
    sigmoid_kernel<<<(T_LEN * NH * 3 + 255) / 256, 256>>>(g, T_LEN * NH * 3);

    // compression
    compress_kernel<<<(NB * HKV * DIM + 255) / 256, 256>>>(k, v, kc, vc);

    // compressed attention + topk (also initializes d_o)
    cmp_attn_kernel<<<dim3(T_LEN, HKV), 256>>>(q, kc, vc, g, o, ti, tc);

    // selected + sliding window (accumulate into d_o)
    slc_attn_kernel<<<dim3(T_LEN, HKV), 512>>>(q, k, v, g, ti, tc, o);
    swa_attn_kernel<<<dim3(T_LEN, HKV), 512>>>(q, k, v, g, o);

    // output projection
    sgemm64<<<dim3(HID / 64, T_LEN / 64), 256>>>(o, Wo, out, T_LEN, HID, NH * DIM);
}

// round 7
// speedup vs baseline: 1.0026x; 1.0026x over previous
#include <cuda_runtime.h>
#include <cuda_bf16.h>
#include <math.h>

// ---------------- problem constants ----------------
#define T_LEN   1024
#define HID     2048
#define NH      64
#define HKV     4
#define GQ      16      // heads per kv group
#define DIM     64
#define BS      64      // block size
#define NB      16      // T / BS
#define SSEL    8       // top-k blocks
#define WIN     512     // sliding window
#define SCALE   0.125f  // 64^-0.5
#define NEG     -1e30f

// ---------------- scratch (device globals; no allocation) ----------------
__device__ float d_q[T_LEN * NH * DIM];       // roped q
__device__ float d_k[T_LEN * HKV * DIM];      // roped k
__device__ float d_v[T_LEN * HKV * DIM];
__device__ float d_g[T_LEN * NH * 3];         // sigmoid gates
__device__ float d_kc[NB * HKV * DIM];
__device__ float d_vc[NB * HKV * DIM];
__device__ int   d_topidx[T_LEN * HKV * SSEL];
__device__ int   d_topcnt[T_LEN * HKV];
__device__ float d_o[T_LEN * NH * DIM];       // gated combined output

// ---------------- generic tiled SGEMM: C[M,N] = A[M,K] @ B[K,N] ----------
// 64x64 tile, BK=16, 256 threads, 4x4 microtile, float4 IO.
__global__ void sgemm64(const float* __restrict__ A, const float* __restrict__ B,
                        float* __restrict__ C, int M, int N, int K) {
    __shared__ float As[16][64];
    __shared__ float Bs[16][64];
    const int tid = threadIdx.x;
    const int tx = tid & 15, ty = tid >> 4;
    const int row0 = blockIdx.y * 64, col0 = blockIdx.x * 64;

    const int ar = tid >> 2;            // 0..63
    const int ac = (tid & 3) * 4;       // 0..12
    const int br = tid >> 4;            // 0..15
    const int bc = (tid & 15) * 4;      // 0..60

    float acc[4][4];
#pragma unroll
    for (int i = 0; i < 4; i++)
#pragma unroll
        for (int j = 0; j < 4; j++) acc[i][j] = 0.f;

    for (int kk = 0; kk < K; kk += 16) {
        float4 av = *reinterpret_cast<const float4*>(&A[(size_t)(row0 + ar) * K + kk + ac]);
        float4 bv = *reinterpret_cast<const float4*>(&B[(size_t)(kk + br) * N + col0 + bc]);
        __syncthreads();
        As[ac + 0][ar] = av.x; As[ac + 1][ar] = av.y;
        As[ac + 2][ar] = av.z; As[ac + 3][ar] = av.w;
        *reinterpret_cast<float4*>(&Bs[br][bc]) = bv;
        __syncthreads();
#pragma unroll
        for (int k = 0; k < 16; k++) {
            float a0 = As[k][ty * 4 + 0], a1 = As[k][ty * 4 + 1];
            float a2 = As[k][ty * 4 + 2], a3 = As[k][ty * 4 + 3];
            float b0 = Bs[k][tx * 4 + 0], b1 = Bs[k][tx * 4 + 1];
            float b2 = Bs[k][tx * 4 + 2], b3 = Bs[k][tx * 4 + 3];
            acc[0][0] += a0 * b0; acc[0][1] += a0 * b1; acc[0][2] += a0 * b2; acc[0][3] += a0 * b3;
            acc[1][0] += a1 * b0; acc[1][1] += a1 * b1; acc[1][2] += a1 * b2; acc[1][3] += a1 * b3;
            acc[2][0] += a2 * b0; acc[2][1] += a2 * b1; acc[2][2] += a2 * b2; acc[2][3] += a2 * b3;
            acc[3][0] += a3 * b0; acc[3][1] += a3 * b1; acc[3][2] += a3 * b2; acc[3][3] += a3 * b3;
        }
    }
#pragma unroll
    for (int i = 0; i < 4; i++) {
        float4 v = make_float4(acc[i][0], acc[i][1], acc[i][2], acc[i][3]);
        *reinterpret_cast<float4*>(&C[(size_t)(row0 + ty * 4 + i) * N + col0 + tx * 4]) = v;
    }
}

// ---------------- RoPE (in place) ----------------
// x layout: [T, nheads, 64]; pair (i, i+32).
__global__ void rope_kernel(float* __restrict__ x, int nheads) {
    int idx = blockIdx.x * blockDim.x + threadIdx.x;
    int total = T_LEN * nheads * 32;
    if (idx >= total) return;
    int i = idx & 31;
    int th = idx >> 5;          // t*nheads + h
    int t = th / nheads;
    float inv = powf(10000.f, -(float)(2 * i) / 64.f);
    float f = (float)t * inv;
    float sn, cs;
    sincosf(f, &sn, &cs);
    float* p = x + (size_t)th * 64;
    float x1 = p[i], x2 = p[i + 32];
    p[i]      = x1 * cs - x2 * sn;
    p[i + 32] = x1 * sn + x2 * cs;
}

__global__ void sigmoid_kernel(float* __restrict__ g, int n) {
    int idx = blockIdx.x * blockDim.x + threadIdx.x;
    if (idx >= n) return;
    g[idx] = 1.f / (1.f + expf(-g[idx]));
}

// ---------------- block mean pooling ----------------
__global__ void compress_kernel(const float* __restrict__ k, const float* __restrict__ v,
                                float* __restrict__ kc, float* __restrict__ vc) {
    int idx = blockIdx.x * blockDim.x + threadIdx.x;  // NB*HKV*DIM = 4096
    if (idx >= NB * HKV * DIM) return;
    int d = idx & 63;
    int h = (idx >> 6) & 3;
    int n = idx >> 8;
    float sk = 0.f, sv = 0.f;
    for (int j = 0; j < BS; j++) {
        int off = ((n * BS + j) * HKV + h) * DIM + d;
        sk += k[off];
        sv += v[off];
    }
    kc[idx] = sk * (1.f / 64.f);
    vc[idx] = sv * (1.f / 64.f);
}

// ---------------- compressed attention + importance + top-k ----------------
// grid (T, HKV), 256 threads.
__global__ void cmp_attn_kernel(const float* __restrict__ q, const float* __restrict__ kc,
                                const float* __restrict__ vc, const float* __restrict__ gates,
                                float* __restrict__ o, int* __restrict__ topidx,
                                int* __restrict__ topcnt) {
    int t = blockIdx.x, hkv = blockIdx.y, tid = threadIdx.x;
    __shared__ float q_s[GQ * DIM];
    __shared__ float s_s[GQ * NB];
    __shared__ float p_s[GQ * NB];
    __shared__ float imp_s[NB];

    const float* qb = q + ((size_t)t * NH + hkv * GQ) * DIM;
    reinterpret_cast<float4*>(q_s)[tid] = reinterpret_cast<const float4*>(qb)[tid];
    __syncthreads();

    {   // scores
        int g_ = tid >> 4, n = tid & 15;
        float acc = 0.f;
        const float* kr = kc + (n * HKV + hkv) * DIM;
#pragma unroll
        for (int d = 0; d < DIM; d++) acc += q_s[g_ * DIM + d] * kr[d];
        acc *= SCALE;
        bool valid = ((n + 1) * BS - 1) <= t;
        s_s[g_ * NB + n] = valid ? acc : NEG;
    }
    __syncthreads();

    if (tid < GQ) {  // softmax per head
        int g_ = tid;
        if (t < BS - 1) {
            for (int n = 0; n < NB; n++) p_s[g_ * NB + n] = 0.f;
        } else {
            float m = NEG;
            for (int n = 0; n < NB; n++) m = fmaxf(m, s_s[g_ * NB + n]);
            float sum = 0.f;
            float e[NB];
            for (int n = 0; n < NB; n++) { e[n] = expf(s_s[g_ * NB + n] - m); sum += e[n]; }
            float inv = 1.f / sum;
            for (int n = 0; n < NB; n++) p_s[g_ * NB + n] = e[n] * inv;
        }
    }
    __syncthreads();

    if (tid < NB) {  // importance per block
        int n = tid;
        float s = 0.f;
        for (int g_ = 0; g_ < GQ; g_++) s += p_s[g_ * NB + n];
        imp_s[n] = s;
    }
    __syncthreads();

    {   // gated o_cmp (initializes d_o)
        int g_ = tid >> 4, dq = tid & 15;
        float gate = gates[((size_t)t * NH + hkv * GQ + g_) * 3 + 0];
#pragma unroll
        for (int r = 0; r < 4; r++) {
            int d = dq * 4 + r;
            float val = 0.f;
            for (int n = 0; n < NB; n++) val += p_s[g_ * NB + n] * vc[(n * HKV + hkv) * DIM + d];
            o[((size_t)t * NH + hkv * GQ + g_) * DIM + d] = gate * val;
        }
    }

    if (tid == 0) {  // top-k (stable: strict > keeps lowest index on tie)
        int cur = t >> 6;
        float sc[NB];
        for (int n = 0; n < NB; n++) {
            if (n > cur) sc[n] = -INFINITY;
            else if (n == 0 || n == cur) sc[n] = INFINITY;
            else sc[n] = imp_s[n];
        }
        bool used[NB];
        for (int n = 0; n < NB; n++) used[n] = false;
        int cnt = 0;
        for (int s = 0; s < SSEL; s++) {
            float bv = -INFINITY; int bi = -1;
            for (int n = 0; n < NB; n++)
                if (!used[n] && sc[n] > bv) { bv = sc[n]; bi = n; }
            if (bi < 0) break;
            used[bi] = true;
            topidx[((size_t)t * HKV + hkv) * SSEL + cnt] = bi;
            cnt++;
        }
        topcnt[t * HKV + hkv] = cnt;
    }
}

// ---------------- selected-blocks attention (flash-style) ----------------
// grid (T, HKV), 512 threads = 16 warps (one per group head).
__global__ void slc_attn_kernel(const float* __restrict__ q, const float* __restrict__ k,
                                const float* __restrict__ v, const float* __restrict__ gates,
                                const int* __restrict__ topidx, const int* __restrict__ topcnt,
                                float* __restrict__ o) {
    int t = blockIdx.x, hkv = blockIdx.y, tid = threadIdx.x;
    int g_ = tid >> 5, lane = tid & 31;
    __shared__ float q_s[GQ * DIM];
    __shared__ float K_s[64 * 65];
    __shared__ float V_s[64 * 65];
    __shared__ float p_s[GQ * 64];

    if (tid < 256) {
        const float* qb = q + ((size_t)t * NH + hkv * GQ) * DIM;
        reinterpret_cast<float4*>(q_s)[tid] = reinterpret_cast<const float4*>(qb)[tid];
    }

    int cnt = topcnt[t * HKV + hkv];
    float m = NEG, l = 0.f, a0 = 0.f, a1 = 0.f;

    for (int s = 0; s < cnt; s++) {
        int n = topidx[((size_t)t * HKV + hkv) * SSEL + s];
        __syncthreads();
#pragma unroll
        for (int r = 0; r < 8; r++) {
            int e = tid + r * 512;
            int row = e >> 6, d = e & 63;
            int gidx = ((n * BS + row) * HKV + hkv) * DIM + d;
            K_s[row * 65 + d] = k[gidx];
            V_s[row * 65 + d] = v[gidx];
        }
        __syncthreads();

        const float* qg = q_s + g_ * DIM;
        float s0 = 0.f, s1 = 0.f;
#pragma unroll
        for (int d = 0; d < DIM; d++) {
            float qd = qg[d];
            s0 += qd * K_s[lane * 65 + d];
            s1 += qd * K_s[(lane + 32) * 65 + d];
        }
        s0 *= SCALE; s1 *= SCALE;
        int pos0 = n * BS + lane, pos1 = pos0 + 32;
        if (pos0 > t) s0 = NEG;
        if (pos1 > t) s1 = NEG;

        float mx = fmaxf(s0, s1);
#pragma unroll
        for (int off = 16; off; off >>= 1) mx = fmaxf(mx, __shfl_xor_sync(0xffffffffu, mx, off));
        float m_new = fmaxf(m, mx);
        float corr = __expf(m - m_new);
        float p0 = __expf(s0 - m_new), p1 = __expf(s1 - m_new);
        p_s[g_ * 64 + lane] = p0;
        p_s[g_ * 64 + lane + 32] = p1;
        float ps = p0 + p1;
#pragma unroll
        for (int off = 16; off; off >>= 1) ps += __shfl_xor_sync(0xffffffffu, ps, off);
        l = l * corr + ps;
        __syncwarp();
        float acc0 = 0.f, acc1 = 0.f;
#pragma unroll
        for (int j = 0; j < 64; j++) {
            float pj = p_s[g_ * 64 + j];
            acc0 += pj * V_s[j * 65 + lane];
            acc1 += pj * V_s[j * 65 + lane + 32];
        }
        a0 = a0 * corr + acc0;
        a1 = a1 * corr + acc1;
        m = m_new;
    }

    float gate = gates[((size_t)t * NH + hkv * GQ + g_) * 3 + 1];
    float inv = (l > 0.f) ? 1.f / l : 0.f;
    size_t ob = ((size_t)t * NH + hkv * GQ + g_) * DIM;
    o[ob + lane]      += gate * a0 * inv;
    o[ob + lane + 32] += gate * a1 * inv;
}

// ---------------- sliding-window attention ----------------
__global__ void swa_attn_kernel(const float* __restrict__ q, const float* __restrict__ k,
                                const float* __restrict__ v, const float* __restrict__ gates,
                                float* __restrict__ o) {
    int t = blockIdx.x, hkv = blockIdx.y, tid = threadIdx.x;
    int g_ = tid >> 5, lane = tid & 31;
    __shared__ float q_s[GQ * DIM];
    __shared__ float K_s[64 * 65];
    __shared__ float V_s[64 * 65];
    __shared__ float p_s[GQ * 64];

    if (tid < 256) {
        const float* qb = q + ((size_t)t * NH + hkv * GQ) * DIM;
        reinterpret_cast<float4*>(q_s)[tid] = reinterpret_cast<const float4*>(qb)[tid];
    }

    int start = t - (WIN - 1); if (start < 0) start = 0;
    int nch = ((t - start) >> 6) + 1;
    float m = NEG, l = 0.f, a0 = 0.f, a1 = 0.f;

    for (int c = 0; c < nch; c++) {
        int p0r = start + c * 64;
        __syncthreads();
#pragma unroll
        for (int r = 0; r < 8; r++) {
            int e = tid + r * 512;
            int row = e >> 6, d = e & 63;
            int gidx = ((p0r + row) * HKV + hkv) * DIM + d;
            K_s[row * 65 + d] = k[gidx];
            V_s[row * 65 + d] = v[gidx];
        }
        __syncthreads();

        const float* qg = q_s + g_ * DIM;
        float s0 = 0.f, s1 = 0.f;
#pragma unroll
        for (int d = 0; d < DIM; d++) {
            float qd = qg[d];
            s0 += qd * K_s[lane * 65 + d];
            s1 += qd * K_s[(lane + 32) * 65 + d];
        }
        s0 *= SCALE; s1 *= SCALE;
        int pos0 = p0r + lane, pos1 = pos0 + 32;
        if (pos0 > t) s0 = NEG;
        if (pos1 > t) s1 = NEG;

        float mx = fmaxf(s0, s1);
#pragma unroll
        for (int off = 16; off; off >>= 1) mx = fmaxf(mx, __shfl_xor_sync(0xffffffffu, mx, off));
        float m_new = fmaxf(m, mx);
        float corr = __expf(m - m_new);
        float p0 = __expf(s0 - m_new), p1 = __expf(s1 - m_new);
        p_s[g_ * 64 + lane] = p0;
        p_s[g_ * 64 + lane + 32] = p1;
        float ps = p0 + p1;
#pragma unroll
        for (int off = 16; off; off >>= 1) ps += __shfl_xor_sync(0xffffffffu, ps, off);
        l = l * corr + ps;
        __syncwarp();
        float acc0 = 0.f, acc1 = 0.f;
#pragma unroll
        for (int j = 0; j < 64; j++) {
            float pj = p_s[g_ * 64 + j];
            acc0 += pj * V_s[j * 65 + lane];
            acc1 += pj * V_s[j * 65 + lane + 32];
        }
        a0 = a0 * corr + acc0;
        a1 = a1 * corr + acc1;
        m = m_new;
    }

    float gate = gates[((size_t)t * NH + hkv * GQ + g_) * 3 + 2];
    float inv = (l > 0.f) ? 1.f / l : 0.f;
    size_t ob = ((size_t)t * NH + hkv * GQ + g_) * DIM;
    o[ob + lane]      += gate * a0 * inv;
    o[ob + lane + 32] += gate * a1 * inv;
}

// ---------------- launch ----------------
extern "C" void kernel_launch(void* const* d_in, const int* in_sizes, int n_in,
                              void* d_out, int out_size) {
    const float* x  = (const float*)d_in[0];
    const float* Wq = (const float*)d_in[1];
    const float* Wk = (const float*)d_in[2];
    const float* Wv = (const float*)d_in[3];
    const float* Wg = (const float*)d_in[4];
    const float* Wo = (const float*)d_in[5];
    float* out = (float*)d_out;

    float *q, *k, *v, *g, *kc, *vc, *o;
    int *ti, *tc;
    cudaGetSymbolAddress((void**)&q,  d_q);
    cudaGetSymbolAddress((void**)&k,  d_k);
    cudaGetSymbolAddress((void**)&v,  d_v);
    cudaGetSymbolAddress((void**)&g,  d_g);
    cudaGetSymbolAddress((void**)&kc, d_kc);
    cudaGetSymbolAddress((void**)&vc, d_vc);
    cudaGetSymbolAddress((void**)&o,  d_o);
    cudaGetSymbolAddress((void**)&ti, d_topidx);
    cudaGetSymbolAddress((void**)&tc, d_topcnt);

    // projections
    sgemm64<<<dim3(NH * DIM / 64, T_LEN / 64), 256>>>(x, Wq, q, T_LEN, NH * DIM, HID);
    sgemm64<<<dim3(HKV * DIM / 64, T_LEN / 64), 256>>>(x, Wk, k, T_LEN, HKV * DIM, HID);
    sgemm64<<<dim3(HKV * DIM / 64, T_LEN / 64), 256>>>(x, Wv, v, T_LEN, HKV * DIM, HID);
    sgemm64<<<dim3(NH * 3 / 64, T_LEN / 64), 256>>>(x, Wg, g, T_LEN, NH * 3, HID);

    // rope + gates
    rope_kernel<<<(T_LEN * NH * 32 + 255) / 256, 256>>>(q, NH);
    rope_kernel<<<(T_LEN * HKV * 32 + 255) / 256, 256>>>(k, HKV);
    sigmoid_kernel<<<(T_LEN * NH * 3 + 255) / 256, 256>>>(g, T_LEN * NH * 3);

    // compression
    compress_kernel<<<(NB * HKV * DIM + 255) / 256, 256>>>(k, v, kc, vc);

    // compressed attention + topk (also initializes d_o)
    cmp_attn_kernel<<<dim3(T_LEN, HKV), 256>>>(q, kc, vc, g, o, ti, tc);

    // selected + sliding window (accumulate into d_o)
    slc_attn_kernel<<<dim3(T_LEN, HKV), 512>>>(q, k, v, g, ti, tc, o);
    swa_attn_kernel<<<dim3(T_LEN, HKV), 512>>>(q, k, v, g, o);

    // output projection
    sgemm64<<<dim3(HID / 64, T_LEN / 64), 256>>>(o, Wo, out, T_LEN, HID, NH * DIM);
}

// round 8
// speedup vs baseline: 1.0030x; 1.0004x over previous
#include <cuda_runtime.h>
#include <cuda_bf16.h>
#include <math.h>

// ---------------- problem constants ----------------
#define T_LEN   1024
#define HID     2048
#define NH      64
#define HKV     4
#define GQ      16      // heads per kv group
#define DIM     64
#define BS      64      // block size
#define NB      16      // T / BS
#define SSEL    8       // top-k blocks
#define WIN     512     // sliding window
#define SCALE   0.125f  // 64^-0.5
#define NEG     -1e30f

// ---------------- scratch (device globals; no allocation) ----------------
__device__ float d_q[T_LEN * NH * DIM];       // roped q
__device__ float d_k[T_LEN * HKV * DIM];      // roped k
__device__ float d_v[T_LEN * HKV * DIM];
__device__ float d_g[T_LEN * NH * 3];         // sigmoid gates
__device__ float d_kc[NB * HKV * DIM];
__device__ float d_vc[NB * HKV * DIM];
__device__ int   d_topidx[T_LEN * HKV * SSEL];
__device__ int   d_topcnt[T_LEN * HKV];
__device__ float d_o[T_LEN * NH * DIM];       // gated combined output

// ---------------- generic tiled SGEMM: C[M,N] = A[M,K] @ B[K,N] ----------
// 64x64 tile, BK=16, 256 threads, 4x4 microtile, float4 IO.
__global__ void sgemm64(const float* __restrict__ A, const float* __restrict__ B,
                        float* __restrict__ C, int M, int N, int K) {
    __shared__ float As[16][64];
    __shared__ float Bs[16][64];
    const int tid = threadIdx.x;
    const int tx = tid & 15, ty = tid >> 4;
    const int row0 = blockIdx.y * 64, col0 = blockIdx.x * 64;

    const int ar = tid >> 2;            // 0..63
    const int ac = (tid & 3) * 4;       // 0..12
    const int br = tid >> 4;            // 0..15
    const int bc = (tid & 15) * 4;      // 0..60

    float acc[4][4];
#pragma unroll
    for (int i = 0; i < 4; i++)
#pragma unroll
        for (int j = 0; j < 4; j++) acc[i][j] = 0.f;

    for (int kk = 0; kk < K; kk += 16) {
        float4 av = *reinterpret_cast<const float4*>(&A[(size_t)(row0 + ar) * K + kk + ac]);
        float4 bv = *reinterpret_cast<const float4*>(&B[(size_t)(kk + br) * N + col0 + bc]);
        __syncthreads();
        As[ac + 0][ar] = av.x; As[ac + 1][ar] = av.y;
        As[ac + 2][ar] = av.z; As[ac + 3][ar] = av.w;
        *reinterpret_cast<float4*>(&Bs[br][bc]) = bv;
        __syncthreads();
#pragma unroll
        for (int k = 0; k < 16; k++) {
            float a0 = As[k][ty * 4 + 0], a1 = As[k][ty * 4 + 1];
            float a2 = As[k][ty * 4 + 2], a3 = As[k][ty * 4 + 3];
            float b0 = Bs[k][tx * 4 + 0], b1 = Bs[k][tx * 4 + 1];
            float b2 = Bs[k][tx * 4 + 2], b3 = Bs[k][tx * 4 + 3];
            acc[0][0] += a0 * b0; acc[0][1] += a0 * b1; acc[0][2] += a0 * b2; acc[0][3] += a0 * b3;
            acc[1][0] += a1 * b0; acc[1][1] += a1 * b1; acc[1][2] += a1 * b2; acc[1][3] += a1 * b3;
            acc[2][0] += a2 * b0; acc[2][1] += a2 * b1; acc[2][2] += a2 * b2; acc[2][3] += a2 * b3;
            acc[3][0] += a3 * b0; acc[3][1] += a3 * b1; acc[3][2] += a3 * b2; acc[3][3] += a3 * b3;
        }
    }
#pragma unroll
    for (int i = 0; i < 4; i++) {
        float4 v = make_float4(acc[i][0], acc[i][1], acc[i][2], acc[i][3]);
        *reinterpret_cast<float4*>(&C[(size_t)(row0 + ty * 4 + i) * N + col0 + tx * 4]) = v;
    }
}

// ---------------- RoPE (in place) ----------------
// x layout: [T, nheads, 64]; pair (i, i+32).
__global__ void rope_kernel(float* __restrict__ x, int nheads) {
    int idx = blockIdx.x * blockDim.x + threadIdx.x;
    int total = T_LEN * nheads * 32;
    if (idx >= total) return;
    int i = idx & 31;
    int th = idx >> 5;          // t*nheads + h
    int t = th / nheads;
    float inv = powf(10000.f, -(float)(2 * i) / 64.f);
    float f = (float)t * inv;
    float sn, cs;
    sincosf(f, &sn, &cs);
    float* p = x + (size_t)th * 64;
    float x1 = p[i], x2 = p[i + 32];
    p[i]      = x1 * cs - x2 * sn;
    p[i + 32] = x1 * sn + x2 * cs;
}

__global__ void sigmoid_kernel(float* __restrict__ g, int n) {
    int idx = blockIdx.x * blockDim.x + threadIdx.x;
    if (idx >= n) return;
    g[idx] = 1.f / (1.f + expf(-g[idx]));
}

// ---------------- block mean pooling ----------------
__global__ void compress_kernel(const float* __restrict__ k, const float* __restrict__ v,
                                float* __restrict__ kc, float* __restrict__ vc) {
    int idx = blockIdx.x * blockDim.x + threadIdx.x;  // NB*HKV*DIM = 4096
    if (idx >= NB * HKV * DIM) return;
    int d = idx & 63;
    int h = (idx >> 6) & 3;
    int n = idx >> 8;
    float sk = 0.f, sv = 0.f;
    for (int j = 0; j < BS; j++) {
        int off = ((n * BS + j) * HKV + h) * DIM + d;
        sk += k[off];
        sv += v[off];
    }
    kc[idx] = sk * (1.f / 64.f);
    vc[idx] = sv * (1.f / 64.f);
}

// ---------------- compressed attention + importance + top-k ----------------
// grid (T, HKV), 256 threads.
__global__ void cmp_attn_kernel(const float* __restrict__ q, const float* __restrict__ kc,
                                const float* __restrict__ vc, const float* __restrict__ gates,
                                float* __restrict__ o, int* __restrict__ topidx,
                                int* __restrict__ topcnt) {
    int t = blockIdx.x, hkv = blockIdx.y, tid = threadIdx.x;
    __shared__ float q_s[GQ * DIM];
    __shared__ float s_s[GQ * NB];
    __shared__ float p_s[GQ * NB];
    __shared__ float imp_s[NB];

    const float* qb = q + ((size_t)t * NH + hkv * GQ) * DIM;
    reinterpret_cast<float4*>(q_s)[tid] = reinterpret_cast<const float4*>(qb)[tid];
    __syncthreads();

    {   // scores
        int g_ = tid >> 4, n = tid & 15;
        float acc = 0.f;
        const float* kr = kc + (n * HKV + hkv) * DIM;
#pragma unroll
        for (int d = 0; d < DIM; d++) acc += q_s[g_ * DIM + d] * kr[d];
        acc *= SCALE;
        bool valid = ((n + 1) * BS - 1) <= t;
        s_s[g_ * NB + n] = valid ? acc : NEG;
    }
    __syncthreads();

    if (tid < GQ) {  // softmax per head
        int g_ = tid;
        if (t < BS - 1) {
            for (int n = 0; n < NB; n++) p_s[g_ * NB + n] = 0.f;
        } else {
            float m = NEG;
            for (int n = 0; n < NB; n++) m = fmaxf(m, s_s[g_ * NB + n]);
            float sum = 0.f;
            float e[NB];
            for (int n = 0; n < NB; n++) { e[n] = expf(s_s[g_ * NB + n] - m); sum += e[n]; }
            float inv = 1.f / sum;
            for (int n = 0; n < NB; n++) p_s[g_ * NB + n] = e[n] * inv;
        }
    }
    __syncthreads();

    if (tid < NB) {  // importance per block
        int n = tid;
        float s = 0.f;
        for (int g_ = 0; g_ < GQ; g_++) s += p_s[g_ * NB + n];
        imp_s[n] = s;
    }
    __syncthreads();

    {   // gated o_cmp (initializes d_o)
        int g_ = tid >> 4, dq = tid & 15;
        float gate = gates[((size_t)t * NH + hkv * GQ + g_) * 3 + 0];
#pragma unroll
        for (int r = 0; r < 4; r++) {
            int d = dq * 4 + r;
            float val = 0.f;
            for (int n = 0; n < NB; n++) val += p_s[g_ * NB + n] * vc[(n * HKV + hkv) * DIM + d];
            o[((size_t)t * NH + hkv * GQ + g_) * DIM + d] = gate * val;
        }
    }

    if (tid == 0) {  // top-k (stable: strict > keeps lowest index on tie)
        int cur = t >> 6;
        float sc[NB];
        for (int n = 0; n < NB; n++) {
            if (n > cur) sc[n] = -INFINITY;
            else if (n == 0 || n == cur) sc[n] = INFINITY;
            else sc[n] = imp_s[n];
        }
        bool used[NB];
        for (int n = 0; n < NB; n++) used[n] = false;
        int cnt = 0;
        for (int s = 0; s < SSEL; s++) {
            float bv = -INFINITY; int bi = -1;
            for (int n = 0; n < NB; n++)
                if (!used[n] && sc[n] > bv) { bv = sc[n]; bi = n; }
            if (bi < 0) break;
            used[bi] = true;
            topidx[((size_t)t * HKV + hkv) * SSEL + cnt] = bi;
            cnt++;
        }
        topcnt[t * HKV + hkv] = cnt;
    }
}

// ---------------- selected-blocks attention (flash-style) ----------------
// grid (T, HKV), 512 threads = 16 warps (one per group head).
__global__ void slc_attn_kernel(const float* __restrict__ q, const float* __restrict__ k,
                                const float* __restrict__ v, const float* __restrict__ gates,
                                const int* __restrict__ topidx, const int* __restrict__ topcnt,
                                float* __restrict__ o) {
    int t = blockIdx.x, hkv = blockIdx.y, tid = threadIdx.x;
    int g_ = tid >> 5, lane = tid & 31;
    __shared__ float q_s[GQ * DIM];
    __shared__ float K_s[64 * 65];
    __shared__ float V_s[64 * 65];
    __shared__ float p_s[GQ * 64];

    if (tid < 256) {
        const float* qb = q + ((size_t)t * NH + hkv * GQ) * DIM;
        reinterpret_cast<float4*>(q_s)[tid] = reinterpret_cast<const float4*>(qb)[tid];
    }

    int cnt = topcnt[t * HKV + hkv];
    float m = NEG, l = 0.f, a0 = 0.f, a1 = 0.f;

    for (int s = 0; s < cnt; s++) {
        int n = topidx[((size_t)t * HKV + hkv) * SSEL + s];
        __syncthreads();
#pragma unroll
        for (int r = 0; r < 8; r++) {
            int e = tid + r * 512;
            int row = e >> 6, d = e & 63;
            int gidx = ((n * BS + row) * HKV + hkv) * DIM + d;
            K_s[row * 65 + d] = k[gidx];
            V_s[row * 65 + d] = v[gidx];
        }
        __syncthreads();

        const float* qg = q_s + g_ * DIM;
        float s0 = 0.f, s1 = 0.f;
#pragma unroll
        for (int d = 0; d < DIM; d++) {
            float qd = qg[d];
            s0 += qd * K_s[lane * 65 + d];
            s1 += qd * K_s[(lane + 32) * 65 + d];
        }
        s0 *= SCALE; s1 *= SCALE;
        int pos0 = n * BS + lane, pos1 = pos0 + 32;
        if (pos0 > t) s0 = NEG;
        if (pos1 > t) s1 = NEG;

        float mx = fmaxf(s0, s1);
#pragma unroll
        for (int off = 16; off; off >>= 1) mx = fmaxf(mx, __shfl_xor_sync(0xffffffffu, mx, off));
        float m_new = fmaxf(m, mx);
        float corr = __expf(m - m_new);
        float p0 = __expf(s0 - m_new), p1 = __expf(s1 - m_new);
        p_s[g_ * 64 + lane] = p0;
        p_s[g_ * 64 + lane + 32] = p1;
        float ps = p0 + p1;
#pragma unroll
        for (int off = 16; off; off >>= 1) ps += __shfl_xor_sync(0xffffffffu, ps, off);
        l = l * corr + ps;
        __syncwarp();
        float acc0 = 0.f, acc1 = 0.f;
#pragma unroll
        for (int j = 0; j < 64; j++) {
            float pj = p_s[g_ * 64 + j];
            acc0 += pj * V_s[j * 65 + lane];
            acc1 += pj * V_s[j * 65 + lane + 32];
        }
        a0 = a0 * corr + acc0;
        a1 = a1 * corr + acc1;
        m = m_new;
    }

    float gate = gates[((size_t)t * NH + hkv * GQ + g_) * 3 + 1];
    float inv = (l > 0.f) ? 1.f / l : 0.f;
    size_t ob = ((size_t)t * NH + hkv * GQ + g_) * DIM;
    o[ob + lane]      += gate * a0 * inv;
    o[ob + lane + 32] += gate * a1 * inv;
}

// ---------------- sliding-window attention ----------------
__global__ void swa_attn_kernel(const float* __restrict__ q, const float* __restrict__ k,
                                const float* __restrict__ v, const float* __restrict__ gates,
                                float* __restrict__ o) {
    int t = blockIdx.x, hkv = blockIdx.y, tid = threadIdx.x;
    int g_ = tid >> 5, lane = tid & 31;
    __shared__ float q_s[GQ * DIM];
    __shared__ float K_s[64 * 65];
    __shared__ float V_s[64 * 65];
    __shared__ float p_s[GQ * 64];

    if (tid < 256) {
        const float* qb = q + ((size_t)t * NH + hkv * GQ) * DIM;
        reinterpret_cast<float4*>(q_s)[tid] = reinterpret_cast<const float4*>(qb)[tid];
    }

    int start = t - (WIN - 1); if (start < 0) start = 0;
    int nch = ((t - start) >> 6) + 1;
    float m = NEG, l = 0.f, a0 = 0.f, a1 = 0.f;

    for (int c = 0; c < nch; c++) {
        int p0r = start + c * 64;
        __syncthreads();
#pragma unroll
        for (int r = 0; r < 8; r++) {
            int e = tid + r * 512;
            int row = e >> 6, d = e & 63;
            int gidx = ((p0r + row) * HKV + hkv) * DIM + d;
            K_s[row * 65 + d] = k[gidx];
            V_s[row * 65 + d] = v[gidx];
        }
        __syncthreads();

        const float* qg = q_s + g_ * DIM;
        float s0 = 0.f, s1 = 0.f;
#pragma unroll
        for (int d = 0; d < DIM; d++) {
            float qd = qg[d];
            s0 += qd * K_s[lane * 65 + d];
            s1 += qd * K_s[(lane + 32) * 65 + d];
        }
        s0 *= SCALE; s1 *= SCALE;
        int pos0 = p0r + lane, pos1 = pos0 + 32;
        if (pos0 > t) s0 = NEG;
        if (pos1 > t) s1 = NEG;

        float mx = fmaxf(s0, s1);
#pragma unroll
        for (int off = 16; off; off >>= 1) mx = fmaxf(mx, __shfl_xor_sync(0xffffffffu, mx, off));
        float m_new = fmaxf(m, mx);
        float corr = __expf(m - m_new);
        float p0 = __expf(s0 - m_new), p1 = __expf(s1 - m_new);
        p_s[g_ * 64 + lane] = p0;
        p_s[g_ * 64 + lane + 32] = p1;
        float ps = p0 + p1;
#pragma unroll
        for (int off = 16; off; off >>= 1) ps += __shfl_xor_sync(0xffffffffu, ps, off);
        l = l * corr + ps;
        __syncwarp();
        float acc0 = 0.f, acc1 = 0.f;
#pragma unroll
        for (int j = 0; j < 64; j++) {
            float pj = p_s[g_ * 64 + j];
            acc0 += pj * V_s[j * 65 + lane];
            acc1 += pj * V_s[j * 65 + lane + 32];
        }
        a0 = a0 * corr + acc0;
        a1 = a1 * corr + acc1;
        m = m_new;
    }

    float gate = gates[((size_t)t * NH + hkv * GQ + g_) * 3 + 2];
    float inv = (l > 0.f) ? 1.f / l : 0.f;
    size_t ob = ((size_t)t * NH + hkv * GQ + g_) * DIM;
    o[ob + lane]      += gate * a0 * inv;
    o[ob + lane + 32] += gate * a1 * inv;
}

// ---------------- launch ----------------
extern "C" void kernel_launch(void* const* d_in, const int* in_sizes, int n_in,
                              void* d_out, int out_size) {
    const float* x  = (const float*)d_in[0];
    const float* Wq = (const float*)d_in[1];
    const float* Wk = (const float*)d_in[2];
    const float* Wv = (const float*)d_in[3];
    const float* Wg = (const float*)d_in[4];
    const float* Wo = (const float*)d_in[5];
    float* out = (float*)d_out;

    float *q, *k, *v, *g, *kc, *vc, *o;
    int *ti, *tc;
    cudaGetSymbolAddress((void**)&q,  d_q);
    cudaGetSymbolAddress((void**)&k,  d_k);
    cudaGetSymbolAddress((void**)&v,  d_v);
    cudaGetSymbolAddress((void**)&g,  d_g);
    cudaGetSymbolAddress((void**)&kc, d_kc);
    cudaGetSymbolAddress((void**)&vc, d_vc);
    cudaGetSymbolAddress((void**)&o,  d_o);
    cudaGetSymbolAddress((void**)&ti, d_topidx);
    cudaGetSymbolAddress((void**)&tc, d_topcnt);

    // projections
    sgemm64<<<dim3(NH * DIM / 64, T_LEN / 64), 256>>>(x, Wq, q, T_LEN, NH * DIM, HID);
    sgemm64<<<dim3(HKV * DIM / 64, T_LEN / 64), 256>>>(x, Wk, k, T_LEN, HKV * DIM, HID);
    sgemm64<<<dim3(HKV * DIM / 64, T_LEN / 64), 256>>>(x, Wv, v, T_LEN, HKV * DIM, HID);
    sgemm64<<<dim3(NH * 3 / 64, T_LEN / 64), 256>>>(x, Wg, g, T_LEN, NH * 3, HID);

    // rope + gates
    rope_kernel<<<(T_LEN * NH * 32 + 255) / 256, 256>>>(q, NH);
    rope_kernel<<<(T_LEN * HKV * 32 + 255) / 256, 256>>>(k, HKV);
    sigmoid_kernel<<<(T_LEN * NH * 3 + 255) / 256, 256>>>(g, T_LEN * NH * 3);

    // compression
    compress_kernel<<<(NB * HKV * DIM + 255) / 256, 256>>>(k, v, kc, vc);

    // compressed attention + topk (also initializes d_o)
    cmp_attn_kernel<<<dim3(T_LEN, HKV), 256>>>(q, kc, vc, g, o, ti, tc);

    // selected + sliding window (accumulate into d_o)
    slc_attn_kernel<<<dim3(T_LEN, HKV), 512>>>(q, k, v, g, ti, tc, o);
    swa_attn_kernel<<<dim3(T_LEN, HKV), 512>>>(q, k, v, g, o);

    // output projection
    sgemm64<<<dim3(HID / 64, T_LEN / 64), 256>>>(o, Wo, out, T_LEN, HID, NH * DIM);
}